// round 1
// baseline (speedup 1.0000x reference)
#include <cuda_runtime.h>

#define BSZ  2
#define SEQ  192
#define DIN  1024
#define DD   128
#define BS   384            // BSZ*SEQ
#define N2   36864          // SEQ*SEQ
#define N3   7077888        // SEQ^3
#define OUTW 14155776       // BSZ*N3  (one output head)

// -------- scratch (device globals: allocation-free) --------
__device__ float g_P[3 * BS * DD];                 // p, sh, st   (3 x 192KB)
__device__ float g_T[(size_t)BS * DD * DD];        // T[bz,i,j]   (25MB)
__device__ float g_M1[(size_t)BS * SEQ * DD];      // M1[bz,x,j]  (38MB)
__device__ float g_S[(size_t)BSZ * N3];            // cop scratch (57MB)

// =======================================================================
// MLP: out[bz, 128] = leaky_relu(x[bz,1024] @ W + b),  3 mats
// grid (12, 3), block 256
// =======================================================================
__global__ void k_mlp(const float* __restrict__ x,
                      const float* __restrict__ W0, const float* __restrict__ b0,
                      const float* __restrict__ W1, const float* __restrict__ b1,
                      const float* __restrict__ W2, const float* __restrict__ b2)
{
    int mat = blockIdx.y;
    const float* W  = (mat == 0) ? W0 : (mat == 1) ? W1 : W2;
    const float* bb = (mat == 0) ? b0 : (mat == 1) ? b1 : b2;
    float* out = g_P + (size_t)mat * BS * DD;

    int row0 = blockIdx.x * 32;
    const float* A = x + (size_t)row0 * DIN;

    __shared__ float xs[32][32];
    __shared__ float ws[32][128];

    int t = threadIdx.x;
    int cx = t & 31, ry = t >> 5;          // cols cx*4..+3, rows ry*4..+3
    float acc[4][4] = {};

    for (int kc = 0; kc < DIN; kc += 32) {
        #pragma unroll
        for (int u = 0; u < 4; u++) {      // 32*32/256
            int idx = t + u * 256;
            xs[idx >> 5][idx & 31] = A[(idx >> 5) * DIN + kc + (idx & 31)];
        }
        #pragma unroll
        for (int u = 0; u < 16; u++) {     // 32*128/256
            int idx = t + u * 256;
            ws[idx >> 7][idx & 127] = W[(kc + (idx >> 7)) * DD + (idx & 127)];
        }
        __syncthreads();
        #pragma unroll
        for (int k = 0; k < 32; k++) {
            float4 wv = *(const float4*)&ws[k][cx * 4];
            #pragma unroll
            for (int m = 0; m < 4; m++) {
                float av = xs[ry * 4 + m][k];
                acc[m][0] += av * wv.x; acc[m][1] += av * wv.y;
                acc[m][2] += av * wv.z; acc[m][3] += av * wv.w;
            }
        }
        __syncthreads();
    }
    float4 bv = *(const float4*)&bb[cx * 4];
    #pragma unroll
    for (int m = 0; m < 4; m++) {
        float4 v;
        v.x = acc[m][0] + bv.x; v.y = acc[m][1] + bv.y;
        v.z = acc[m][2] + bv.z; v.w = acc[m][3] + bv.w;
        v.x = v.x > 0.f ? v.x : 0.1f * v.x;
        v.y = v.y > 0.f ? v.y : 0.1f * v.y;
        v.z = v.z > 0.f ? v.z : 0.1f * v.z;
        v.w = v.w > 0.f ? v.w : 0.1f * v.w;
        *(float4*)&out[(size_t)(row0 + ry * 4 + m) * DD + cx * 4] = v;
    }
}

// =======================================================================
// 64x128 fp32 tile GEMM: C[64,128] = A[64,128] @ B[128,128]
// block 256, per-thread 8 rows x 4 cols
// =======================================================================
__device__ __forceinline__ void gemm64x128(const float* __restrict__ A, int lda,
                                           const float* __restrict__ Bm,
                                           float* __restrict__ C, int ldc)
{
    __shared__ float as[64][32];
    __shared__ float bs[32][128];

    int t = threadIdx.x;
    int cx = t & 31, ry = t >> 5;
    float acc[8][4] = {};

    for (int kc = 0; kc < 128; kc += 32) {
        #pragma unroll
        for (int u = 0; u < 8; u++) {      // 64*32/256
            int idx = t + u * 256;
            as[idx >> 5][idx & 31] = A[(idx >> 5) * lda + kc + (idx & 31)];
        }
        #pragma unroll
        for (int u = 0; u < 16; u++) {     // 32*128/256
            int idx = t + u * 256;
            bs[idx >> 7][idx & 127] = Bm[(kc + (idx >> 7)) * 128 + (idx & 127)];
        }
        __syncthreads();
        #pragma unroll
        for (int k = 0; k < 32; k++) {
            float4 bv = *(const float4*)&bs[k][cx * 4];
            #pragma unroll
            for (int m = 0; m < 8; m++) {
                float av = as[ry * 8 + m][k];
                acc[m][0] += av * bv.x; acc[m][1] += av * bv.y;
                acc[m][2] += av * bv.z; acc[m][3] += av * bv.w;
            }
        }
        __syncthreads();
    }
    #pragma unroll
    for (int m = 0; m < 8; m++) {
        float4 v = make_float4(acc[m][0], acc[m][1], acc[m][2], acc[m][3]);
        *(float4*)&C[(size_t)(ry * 8 + m) * ldc + cx * 4] = v;
    }
}

// T[bz,i,j] = sum_k Z[bz,k] W[i,k,j]     grid (6, 128)
__global__ void k_T(int zsel, const float* __restrict__ W)
{
    int i = blockIdx.y;
    int row0 = blockIdx.x * 64;
    const float* Z = g_P + (size_t)zsel * BS * DD;
    gemm64x128(Z + (size_t)row0 * 128, 128,
               W + (size_t)i * 128 * 128,
               g_T + (size_t)row0 * 16384 + (size_t)i * 128, 16384);
}

// M1[bz,x,j] = sum_i X[b,x,i] T[bz,i,j]  grid (3, 384)
__global__ void k_M1(int xsel)
{
    int bz = blockIdx.y;
    int b = bz / SEQ;
    int row0 = blockIdx.x * 64;
    const float* X = g_P + (size_t)xsel * BS * DD + (size_t)b * SEQ * 128;
    gemm64x128(X + (size_t)row0 * 128, 128,
               g_T + (size_t)bz * 16384,
               g_M1 + (size_t)bz * (SEQ * 128) + (size_t)row0 * 128, 128);
}

// =======================================================================
// S[bz,x,y] = sum_j M1[bz,x,j] * Y[b,y,j]    grid (3, 384), block 256
// per-thread 8 rows x 6 cols (cols n*32+cx -> coalesced stores,
// conflict-free smem reads)
// =======================================================================
__global__ void k_S(int ysel, float* __restrict__ dstOut, int useS)
{
    int bz = blockIdx.y;
    int b = bz / SEQ;
    int x0 = blockIdx.x * 64;

    const float* A  = g_M1 + (size_t)bz * (SEQ * 128) + (size_t)x0 * 128;
    const float* Yb = g_P + (size_t)ysel * BS * DD + (size_t)b * SEQ * 128;
    float* dst = useS ? g_S : dstOut;
    float* C = dst + (size_t)bz * N2 + (size_t)x0 * SEQ;

    __shared__ float as[64][32];
    __shared__ float ys[192][33];

    int t = threadIdx.x;
    int cx = t & 31, ry = t >> 5;
    float acc[8][6] = {};

    for (int kc = 0; kc < 128; kc += 32) {
        #pragma unroll
        for (int u = 0; u < 8; u++) {
            int idx = t + u * 256;
            as[idx >> 5][idx & 31] = A[(idx >> 5) * 128 + kc + (idx & 31)];
        }
        #pragma unroll
        for (int u = 0; u < 24; u++) {     // 192*32/256
            int idx = t + u * 256;
            ys[idx >> 5][idx & 31] = Yb[(idx >> 5) * 128 + kc + (idx & 31)];
        }
        __syncthreads();
        #pragma unroll
        for (int k = 0; k < 32; k++) {
            float yv[6];
            #pragma unroll
            for (int n = 0; n < 6; n++) yv[n] = ys[n * 32 + cx][k];
            #pragma unroll
            for (int m = 0; m < 8; m++) {
                float av = as[ry * 8 + m][k];
                #pragma unroll
                for (int n = 0; n < 6; n++) acc[m][n] += av * yv[n];
            }
        }
        __syncthreads();
    }
    #pragma unroll
    for (int m = 0; m < 8; m++)
        #pragma unroll
        for (int n = 0; n < 6; n++)
            C[(size_t)(ry * 8 + m) * SEQ + n * 32 + cx] = acc[m][n];
}

// =======================================================================
// In-place symmetrize: A[.., x, y] = A[.., y, x] for x > y (keep upper)
// grid (21, 384), block (32, 8)
// =======================================================================
__global__ void k_sym(float* __restrict__ Aout, int useS)
{
    float* M = (useS ? g_S : Aout) + (size_t)blockIdx.y * N2;
    int p = blockIdx.x;
    int ti = 0;
    while ((ti + 1) * (ti + 2) / 2 <= p) ti++;
    int tj = p - ti * (ti + 1) / 2;       // ti >= tj
    int xs0 = ti * 32, ys0 = tj * 32;

    __shared__ float tile[32][33];
    int tx = threadIdx.x, ty = threadIdx.y;
    #pragma unroll
    for (int r = 0; r < 4; r++)
        tile[ty + r * 8][tx] = M[(size_t)(ys0 + ty + r * 8) * SEQ + xs0 + tx];
    __syncthreads();
    #pragma unroll
    for (int r = 0; r < 4; r++) {
        int xg = xs0 + ty + r * 8, yg = ys0 + tx;
        if (xg > yg) M[(size_t)xg * SEQ + yg] = tile[tx][ty + r * 8];
    }
}

// =======================================================================
// Permute (0,2,3,1): out[b, q=x*S+y, z] = g_S[b, z, q]
// grid (1152, 6, 2), block (32, 8)
// =======================================================================
__global__ void k_perm(float* __restrict__ outw)
{
    int b = blockIdx.z;
    const float* in = g_S + (size_t)b * N3;
    float* o = outw + (size_t)b * N3;
    int q0 = blockIdx.x * 32, z0 = blockIdx.y * 32;

    __shared__ float tile[32][33];
    int tx = threadIdx.x, ty = threadIdx.y;
    #pragma unroll
    for (int r = 0; r < 4; r++)
        tile[ty + r * 8][tx] = in[(size_t)(z0 + ty + r * 8) * N2 + q0 + tx];
    __syncthreads();
    #pragma unroll
    for (int r = 0; r < 4; r++)
        o[(size_t)(q0 + ty + r * 8) * SEQ + z0 + tx] = tile[tx][ty + r * 8];
}

// =======================================================================
extern "C" void kernel_launch(void* const* d_in, const int* in_sizes, int n_in,
                              void* d_out, int out_size)
{
    const float* x  = (const float*)d_in[0];
    const float* Wp = (const float*)d_in[1];
    const float* bp = (const float*)d_in[2];
    const float* Wh = (const float*)d_in[3];
    const float* bh = (const float*)d_in[4];
    const float* Wt = (const float*)d_in[5];
    const float* bt = (const float*)d_in[6];
    float* out = (float*)d_out;

    // p=0, sh=1, st=2
    k_mlp<<<dim3(12, 3), 256>>>(x, Wp, bp, Wh, bh, Wt, bt);

    // per-head config: {xsel, ysel, zsel, weight input idx, sym?, cop(perm)?}
    struct Cfg { int xs, ys, zs, widx, sym, cop; };
    const Cfg cfgs[6] = {
        {1, 2, 0,  7, 1, 0},   // span_psh = sym(tri(sh, st, p, W_span_ph))
        {1, 2, 0,  8, 1, 0},   // span_pst = sym(tri(sh, st, p, W_span_pt))
        {1, 1, 0,  9, 1, 0},   // ph_sib   = sym(tri(sh, sh, p, W_ph_sib))
        {2, 2, 0, 10, 1, 0},   // pt_sib   = sym(tri(st, st, p, W_pt_sib))
        {0, 0, 1, 11, 0, 1},   // ph_cop   = perm(tri(p, p, sh, W_ph_cop))
        {0, 0, 2, 12, 1, 1},   // pt_cop   = perm(sym(tri(p, p, st, W_pt_cop)))
    };

    for (int w = 0; w < 6; w++) {
        const Cfg& c = cfgs[w];
        const float* Ww = (const float*)d_in[c.widx];
        float* dstw = out + (size_t)w * OUTW;

        k_T <<<dim3(6, 128), 256>>>(c.zs, Ww);
        k_M1<<<dim3(3, 384), 256>>>(c.xs);
        k_S <<<dim3(3, 384), 256>>>(c.ys, dstw, c.cop);
        if (c.sym) k_sym<<<dim3(21, 384), dim3(32, 8)>>>(dstw, c.cop);
        if (c.cop) k_perm<<<dim3(1152, 6, 2), dim3(32, 8)>>>(dstw);
    }
}

// round 3
// speedup vs baseline: 1.8497x; 1.8497x over previous
#include <cuda_runtime.h>
#include <cuda_bf16.h>
#include <cstdint>

#define BSZ  2
#define SEQ  192
#define DIN  1024
#define DD   128
#define BS   384            // BSZ*SEQ
#define N2   36864          // SEQ*SEQ
#define N3   7077888        // SEQ^3
#define OUTW 14155776       // BSZ*N3  (one output head)

// -------- scratch (device globals: allocation-free) --------
__device__ float g_P[3 * BS * DD];                      // p, sh, st (fp32)
__device__ float g_S[(size_t)BSZ * N3];                 // cop scratch (57MB)
__device__ unsigned short g_Th[(size_t)BS * DD * DD];   // T hi  [bz][i][j] bf16
__device__ unsigned short g_Tl[(size_t)BS * DD * DD];   // T lo
__device__ unsigned short g_Yth[(size_t)BSZ * DD * SEQ];// Y^T hi [b][j][y]
__device__ unsigned short g_Ytl[(size_t)BSZ * DD * SEQ];// Y^T lo

// ======================= helpers =======================
__device__ __forceinline__ uint32_t smem_to_u32(const void* p) {
    uint32_t a;
    asm("{ .reg .u64 t; cvta.to.shared.u64 t, %1; cvt.u32.u64 %0, t; }" : "=r"(a) : "l"(p));
    return a;
}
__device__ __forceinline__ void ldsm4(uint32_t* r, uint32_t a) {
    asm volatile("ldmatrix.sync.aligned.m8n8.x4.shared.b16 {%0,%1,%2,%3}, [%4];"
        : "=r"(r[0]), "=r"(r[1]), "=r"(r[2]), "=r"(r[3]) : "r"(a));
}
__device__ __forceinline__ void ldsm2t(uint32_t* r, uint32_t a) {
    asm volatile("ldmatrix.sync.aligned.m8n8.x2.trans.shared.b16 {%0,%1}, [%2];"
        : "=r"(r[0]), "=r"(r[1]) : "r"(a));
}
__device__ __forceinline__ void mma16816(float* c, const uint32_t* a, const uint32_t* b) {
    asm volatile("mma.sync.aligned.m16n8k16.row.col.f32.bf16.bf16.f32 "
        "{%0,%1,%2,%3},{%4,%5,%6,%7},{%8,%9},{%0,%1,%2,%3};"
        : "+f"(c[0]), "+f"(c[1]), "+f"(c[2]), "+f"(c[3])
        : "r"(a[0]), "r"(a[1]), "r"(a[2]), "r"(a[3]), "r"(b[0]), "r"(b[1]));
}
__device__ __forceinline__ uint32_t pack_hl(float a, float b, uint32_t& lo_out) {
    __nv_bfloat16 ha = __float2bfloat16(a), hb = __float2bfloat16(b);
    float ra = a - __bfloat162float(ha), rb = b - __bfloat162float(hb);
    __nv_bfloat16 la = __float2bfloat16(ra), lb = __float2bfloat16(rb);
    lo_out = (uint32_t)__bfloat16_as_ushort(la) | ((uint32_t)__bfloat16_as_ushort(lb) << 16);
    return (uint32_t)__bfloat16_as_ushort(ha) | ((uint32_t)__bfloat16_as_ushort(hb) << 16);
}
// pack 8 consecutive floats -> uint4 hi + uint4 lo (bf16x2 each)
__device__ __forceinline__ void pack8(const float* __restrict__ src, uint4& hv, uint4& lv) {
    uint32_t h[4], l[4];
    #pragma unroll
    for (int e = 0; e < 4; e++) {
        float2 f = *(const float2*)(src + 2 * e);
        h[e] = pack_hl(f.x, f.y, l[e]);
    }
    hv = make_uint4(h[0], h[1], h[2], h[3]);
    lv = make_uint4(l[0], l[1], l[2], l[3]);
}

// warp GEMM: C[MF*16 x NF*8] += Asm(hi/lo) @ Bsm(hi/lo), K=128, bf16 split (3 terms)
// A smem: [rows][128] bf16, 256B/row, chunk-swizzled (chunk ^ (row&7))
// B smem: [k rows][N cols] bf16, BRB bytes/row, same swizzle
template<int MF, int NF, int BRB>
__device__ __forceinline__ void wgemm(uint32_t aH, uint32_t aL,
                                      uint32_t bH, uint32_t bL,
                                      int m0, int n0, int lane,
                                      float C[MF][NF][4])
{
    for (int kk = 0; kk < 8; kk++) {
        uint32_t ah[MF][4], al[MF][4];
        #pragma unroll
        for (int mf = 0; mf < MF; mf++) {
            int r = m0 + mf * 16 + (lane & 15);
            int ck = kk * 2 + (lane >> 4);
            uint32_t off = (uint32_t)(r * 256 + ((ck ^ (r & 7)) << 4));
            ldsm4(ah[mf], aH + off);
            ldsm4(al[mf], aL + off);
        }
        int rb = kk * 16 + (lane & 15);
        #pragma unroll
        for (int nf = 0; nf < NF; nf++) {
            int nc = (n0 >> 3) + nf;
            uint32_t boff = (uint32_t)(rb * BRB + ((nc ^ (rb & 7)) << 4));
            uint32_t bh[2], bl[2];
            ldsm2t(bh, bH + boff);
            ldsm2t(bl, bL + boff);
            #pragma unroll
            for (int mf = 0; mf < MF; mf++) {
                mma16816(C[mf][nf], ah[mf], bh);
                mma16816(C[mf][nf], al[mf], bh);
                mma16816(C[mf][nf], ah[mf], bl);
            }
        }
    }
}

// =======================================================================
// MLP (unchanged from R1)
// =======================================================================
__global__ void k_mlp(const float* __restrict__ x,
                      const float* __restrict__ W0, const float* __restrict__ b0,
                      const float* __restrict__ W1, const float* __restrict__ b1,
                      const float* __restrict__ W2, const float* __restrict__ b2)
{
    int mat = blockIdx.y;
    const float* W  = (mat == 0) ? W0 : (mat == 1) ? W1 : W2;
    const float* bb = (mat == 0) ? b0 : (mat == 1) ? b1 : b2;
    float* out = g_P + (size_t)mat * BS * DD;
    int row0 = blockIdx.x * 32;
    const float* A = x + (size_t)row0 * DIN;
    __shared__ float xs[32][32];
    __shared__ float ws[32][128];
    int t = threadIdx.x;
    int cx = t & 31, ry = t >> 5;
    float acc[4][4] = {};
    for (int kc = 0; kc < DIN; kc += 32) {
        #pragma unroll
        for (int u = 0; u < 4; u++) {
            int idx = t + u * 256;
            xs[idx >> 5][idx & 31] = A[(idx >> 5) * DIN + kc + (idx & 31)];
        }
        #pragma unroll
        for (int u = 0; u < 16; u++) {
            int idx = t + u * 256;
            ws[idx >> 7][idx & 127] = W[(kc + (idx >> 7)) * DD + (idx & 127)];
        }
        __syncthreads();
        #pragma unroll
        for (int k = 0; k < 32; k++) {
            float4 wv = *(const float4*)&ws[k][cx * 4];
            #pragma unroll
            for (int m = 0; m < 4; m++) {
                float av = xs[ry * 4 + m][k];
                acc[m][0] += av * wv.x; acc[m][1] += av * wv.y;
                acc[m][2] += av * wv.z; acc[m][3] += av * wv.w;
            }
        }
        __syncthreads();
    }
    float4 bv = *(const float4*)&bb[cx * 4];
    #pragma unroll
    for (int m = 0; m < 4; m++) {
        float4 v;
        v.x = acc[m][0] + bv.x; v.y = acc[m][1] + bv.y;
        v.z = acc[m][2] + bv.z; v.w = acc[m][3] + bv.w;
        v.x = v.x > 0.f ? v.x : 0.1f * v.x;
        v.y = v.y > 0.f ? v.y : 0.1f * v.y;
        v.z = v.z > 0.f ? v.z : 0.1f * v.z;
        v.w = v.w > 0.f ? v.w : 0.1f * v.w;
        *(float4*)&out[(size_t)(row0 + ry * 4 + m) * DD + cx * 4] = v;
    }
}

// =======================================================================
// Y prep: g_P[ysel][b][y][j] fp32 -> g_Yth/g_Ytl [b][j][y] bf16 hi/lo
// grid (6 ytiles, 4 jtiles, 2 b), block (32,8)
// =======================================================================
__global__ void k_yprep(int ysel)
{
    int b = blockIdx.z;
    int y0 = blockIdx.x * 32, j0 = blockIdx.y * 32;
    const float* src = g_P + (size_t)ysel * BS * DD + (size_t)b * SEQ * DD;
    __shared__ float t[32][33];
    int tx = threadIdx.x, ty = threadIdx.y;
    #pragma unroll
    for (int r = 0; r < 4; r++)
        t[ty + r * 8][tx] = src[(size_t)(y0 + ty + r * 8) * DD + j0 + tx];
    __syncthreads();
    #pragma unroll
    for (int r = 0; r < 4; r++) {
        int jj = ty + r * 8, yy = tx;
        float v = t[yy][jj];
        __nv_bfloat16 h = __float2bfloat16(v);
        __nv_bfloat16 l = __float2bfloat16(v - __bfloat162float(h));
        size_t o = (size_t)b * DD * SEQ + (size_t)(j0 + jj) * SEQ + y0 + yy;
        g_Yth[o] = __bfloat16_as_ushort(h);
        g_Ytl[o] = __bfloat16_as_ushort(l);
    }
}

// =======================================================================
// Stage1: T[bz,i,j] = sum_k Z[bz,k] W[i,k,j]   (HMMA, bf16 split)
// grid (128 i, 3 bz-tiles), 256 threads (8 warps, warp tile 32x64)
// smem: Zh@0 Zl@32768 Wh@65536 Wl@98304 (each 32KB); staging reuses Z.
// =======================================================================
#define S1_ZH 0
#define S1_ZL 32768
#define S1_WH 65536
#define S1_WL 98304
#define S1_SMEM 131072
__global__ void __launch_bounds__(256, 1) k_stage1(int zsel, const float* __restrict__ W)
{
    extern __shared__ __align__(16) char smem[];
    uint32_t sb = smem_to_u32(smem);
    int tid = threadIdx.x, lane = tid & 31, w = tid >> 5;
    int i = blockIdx.x, bz0 = blockIdx.y * 128;
    const float* Z  = g_P + (size_t)zsel * BS * DD + (size_t)bz0 * DD;
    const float* Wi = W + (size_t)i * DD * DD;

    for (int idx = tid; idx < 2048; idx += 256) {
        int r = idx >> 4, c = idx & 15;
        uint32_t off = (uint32_t)(r * 256 + ((c ^ (r & 7)) << 4));
        uint4 hv, lv;
        pack8(Z + (size_t)r * DD + c * 8, hv, lv);
        *(uint4*)(smem + S1_ZH + off) = hv;
        *(uint4*)(smem + S1_ZL + off) = lv;
        pack8(Wi + (size_t)r * DD + c * 8, hv, lv);
        *(uint4*)(smem + S1_WH + off) = hv;
        *(uint4*)(smem + S1_WL + off) = lv;
    }
    __syncthreads();

    float C[2][8][4] = {};
    int m0 = (w >> 1) * 32, n0 = (w & 1) * 64;
    wgemm<2, 8, 256>(sb + S1_ZH, sb + S1_ZL, sb + S1_WH, sb + S1_WL, m0, n0, lane, C);
    __syncthreads();

    // pack C -> staging (hi @0 stride 66 u32, lo @33792)
    uint32_t* stH = (uint32_t*)smem;
    uint32_t* stL = (uint32_t*)(smem + 33792);
    #pragma unroll
    for (int mf = 0; mf < 2; mf++)
        #pragma unroll
        for (int nf = 0; nf < 8; nf++) {
            int row = m0 + mf * 16 + (lane >> 2);
            int col = n0 + nf * 8 + (lane & 3) * 2;
            uint32_t lo0, lo1;
            uint32_t hi0 = pack_hl(C[mf][nf][0], C[mf][nf][1], lo0);
            uint32_t hi1 = pack_hl(C[mf][nf][2], C[mf][nf][3], lo1);
            stH[row * 66 + (col >> 1)] = hi0;       stL[row * 66 + (col >> 1)] = lo0;
            stH[(row + 8) * 66 + (col >> 1)] = hi1; stL[(row + 8) * 66 + (col >> 1)] = lo1;
        }
    __syncthreads();
    for (int idx = tid; idx < 8192; idx += 256) {
        int r = idx >> 6, c = idx & 63;
        size_t go = (size_t)(bz0 + r) * (DD * DD) + (size_t)i * DD + c * 2;
        *(uint32_t*)(g_Th + go) = stH[r * 66 + c];
        *(uint32_t*)(g_Tl + go) = stL[r * 66 + c];
    }
}

// =======================================================================
// Stage 2+3 fused per bz:
//   M1[x,j] = sum_i X[x,i] T[i,j];  S[x,y] = sum_j M1[x,j] Yt[j,y]
// 384 threads (12 warps). Epilogue: sym in-block, coalesced output.
// smem: X/M1 hi@0 lo@49152 ; T hi@98304 lo@131072 ; Y hi@98304 lo@147456
//       Ssm fp32 stride 193 @0 (148224 B)
// =======================================================================
#define S2_XH 0
#define S2_XL 49152
#define S2_TH 98304
#define S2_TL 131072
#define S2_YH 98304
#define S2_YL 147456
#define S23_SMEM 196608
__global__ void __launch_bounds__(384, 1) k_stage23(int xsel, float* __restrict__ dst0,
                                                    int useS, int dosym)
{
    extern __shared__ __align__(16) char smem[];
    uint32_t sb = smem_to_u32(smem);
    int tid = threadIdx.x, lane = tid & 31, w = tid >> 5;
    int bz = blockIdx.x, b = bz / SEQ;

    // ---- load X (192x128 fp32 -> hi/lo swizzled) ----
    const float* Xb = g_P + (size_t)xsel * BS * DD + (size_t)b * SEQ * DD;
    for (int idx = tid; idx < 3072; idx += 384) {
        int r = idx >> 4, c = idx & 15;
        uint32_t off = (uint32_t)(r * 256 + ((c ^ (r & 7)) << 4));
        uint4 hv, lv;
        pack8(Xb + (size_t)r * DD + c * 8, hv, lv);
        *(uint4*)(smem + S2_XH + off) = hv;
        *(uint4*)(smem + S2_XL + off) = lv;
    }
    // ---- load T (already bf16 hi/lo) ----
    const uint4* TH4 = (const uint4*)(g_Th + (size_t)bz * DD * DD);
    const uint4* TL4 = (const uint4*)(g_Tl + (size_t)bz * DD * DD);
    for (int idx = tid; idx < 2048; idx += 384) {
        int r = idx >> 4, c = idx & 15;
        uint32_t off = (uint32_t)(r * 256 + ((c ^ (r & 7)) << 4));
        *(uint4*)(smem + S2_TH + off) = TH4[idx];
        *(uint4*)(smem + S2_TL + off) = TL4[idx];
    }
    __syncthreads();

    // ---- stage2: M1 = X @ T   (warp tile 32x64; 6x2) ----
    float C2[2][8][4] = {};
    {
        int m0 = (w >> 1) * 32, n0 = (w & 1) * 64;
        wgemm<2, 8, 256>(sb + S2_XH, sb + S2_XL, sb + S2_TH, sb + S2_TL, m0, n0, lane, C2);
        __syncthreads();
        // store M1 hi/lo into region0 (overwrites X)
        #pragma unroll
        for (int mf = 0; mf < 2; mf++)
            #pragma unroll
            for (int nf = 0; nf < 8; nf++) {
                int row = m0 + mf * 16 + (lane >> 2);
                int col = n0 + nf * 8 + (lane & 3) * 2;
                uint32_t lo0, lo1;
                uint32_t hi0 = pack_hl(C2[mf][nf][0], C2[mf][nf][1], lo0);
                uint32_t hi1 = pack_hl(C2[mf][nf][2], C2[mf][nf][3], lo1);
                int r2 = row + 8;
                uint32_t o0 = (uint32_t)(row * 256 + (((col >> 3) ^ (row & 7)) << 4) + (col & 7) * 2);
                uint32_t o1 = (uint32_t)(r2 * 256 + (((col >> 3) ^ (r2 & 7)) << 4) + (col & 7) * 2);
                *(uint32_t*)(smem + S2_XH + o0) = hi0;
                *(uint32_t*)(smem + S2_XL + o0) = lo0;
                *(uint32_t*)(smem + S2_XH + o1) = hi1;
                *(uint32_t*)(smem + S2_XL + o1) = lo1;
            }
    }
    // ---- load Y^T (128 rows x 192 cols bf16, 24 chunks/row) ----
    const uint4* YH4 = (const uint4*)(g_Yth + (size_t)b * DD * SEQ);
    const uint4* YL4 = (const uint4*)(g_Ytl + (size_t)b * DD * SEQ);
    for (int idx = tid; idx < 3072; idx += 384) {
        int r = idx / 24, c = idx % 24;
        uint32_t off = (uint32_t)(r * 384 + ((c ^ (r & 7)) << 4));
        *(uint4*)(smem + S2_YH + off) = YH4[idx];
        *(uint4*)(smem + S2_YL + off) = YL4[idx];
    }
    __syncthreads();

    // ---- stage3: S = M1 @ Y^T  (warp tile 48x64; 4x3) ----
    float C3[3][8][4] = {};
    int m3 = (w & 3) * 48, n3 = (w >> 2) * 64;
    wgemm<3, 8, 384>(sb + S2_XH, sb + S2_XL, sb + S2_YH, sb + S2_YL, m3, n3, lane, C3);
    __syncthreads();

    // ---- epilogue: C -> Ssm (stride 193), then sym + coalesced store ----
    float* Ssm = (float*)smem;
    #pragma unroll
    for (int mf = 0; mf < 3; mf++)
        #pragma unroll
        for (int nf = 0; nf < 8; nf++) {
            int row = m3 + mf * 16 + (lane >> 2);
            int col = n3 + nf * 8 + (lane & 3) * 2;
            Ssm[row * 193 + col]           = C3[mf][nf][0];
            Ssm[row * 193 + col + 1]       = C3[mf][nf][1];
            Ssm[(row + 8) * 193 + col]     = C3[mf][nf][2];
            Ssm[(row + 8) * 193 + col + 1] = C3[mf][nf][3];
        }
    __syncthreads();

    float* dst = (useS ? g_S : dst0) + (size_t)bz * N2;
    for (int idx = tid * 4; idx < N2; idx += 384 * 4) {
        int x = idx / SEQ, y = idx % SEQ;
        float4 v;
        if (dosym) {
            v.x = (x <= y)     ? Ssm[x * 193 + y]     : Ssm[y * 193 + x];
            v.y = (x <= y + 1) ? Ssm[x * 193 + y + 1] : Ssm[(y + 1) * 193 + x];
            v.z = (x <= y + 2) ? Ssm[x * 193 + y + 2] : Ssm[(y + 2) * 193 + x];
            v.w = (x <= y + 3) ? Ssm[x * 193 + y + 3] : Ssm[(y + 3) * 193 + x];
        } else {
            v.x = Ssm[x * 193 + y];
            v.y = Ssm[x * 193 + y + 1];
            v.z = Ssm[x * 193 + y + 2];
            v.w = Ssm[x * 193 + y + 3];
        }
        *(float4*)(dst + idx) = v;
    }
}

// =======================================================================
// Permute (0,2,3,1): out[b, q=x*S+y, z] = g_S[b, z, q]
// =======================================================================
__global__ void k_perm(float* __restrict__ outw)
{
    int b = blockIdx.z;
    const float* in = g_S + (size_t)b * N3;
    float* o = outw + (size_t)b * N3;
    int q0 = blockIdx.x * 32, z0 = blockIdx.y * 32;
    __shared__ float tile[32][33];
    int tx = threadIdx.x, ty = threadIdx.y;
    #pragma unroll
    for (int r = 0; r < 4; r++)
        tile[ty + r * 8][tx] = in[(size_t)(z0 + ty + r * 8) * N2 + q0 + tx];
    __syncthreads();
    #pragma unroll
    for (int r = 0; r < 4; r++)
        o[(size_t)(q0 + ty + r * 8) * SEQ + z0 + tx] = tile[tx][ty + r * 8];
}

// =======================================================================
extern "C" void kernel_launch(void* const* d_in, const int* in_sizes, int n_in,
                              void* d_out, int out_size)
{
    const float* x  = (const float*)d_in[0];
    const float* Wp = (const float*)d_in[1];
    const float* bp = (const float*)d_in[2];
    const float* Wh = (const float*)d_in[3];
    const float* bh = (const float*)d_in[4];
    const float* Wt = (const float*)d_in[5];
    const float* bt = (const float*)d_in[6];
    float* out = (float*)d_out;

    static int attr_done = 0;
    if (!attr_done) {
        cudaFuncSetAttribute(k_stage1,  cudaFuncAttributeMaxDynamicSharedMemorySize, S1_SMEM);
        cudaFuncSetAttribute(k_stage23, cudaFuncAttributeMaxDynamicSharedMemorySize, S23_SMEM);
        attr_done = 1;
    }

    k_mlp<<<dim3(12, 3), 256>>>(x, Wp, bp, Wh, bh, Wt, bt);

    struct Cfg { int xs, ys, zs, widx, sym, cop; };
    const Cfg cfgs[6] = {
        {1, 2, 0,  7, 1, 0},   // span_psh = sym(tri(sh, st, p, W_span_ph))
        {1, 2, 0,  8, 1, 0},   // span_pst
        {1, 1, 0,  9, 1, 0},   // ph_sib
        {2, 2, 0, 10, 1, 0},   // pt_sib
        {0, 0, 1, 11, 0, 1},   // ph_cop (no sym)
        {0, 0, 2, 12, 1, 1},   // pt_cop (sym)
    };

    for (int wi = 0; wi < 6; wi++) {
        const Cfg& c = cfgs[wi];
        const float* Ww = (const float*)d_in[c.widx];
        float* dstw = out + (size_t)wi * OUTW;

        k_stage1 <<<dim3(128, 3), 256, S1_SMEM>>>(c.zs, Ww);
        k_yprep  <<<dim3(6, 4, 2), dim3(32, 8)>>>(c.ys);
        k_stage23<<<BS, 384, S23_SMEM>>>(c.xs, dstw, c.cop, c.sym);
        if (c.cop) k_perm<<<dim3(1152, 6, 2), dim3(32, 8)>>>(dstw);
    }
}